// round 13
// baseline (speedup 1.0000x reference)
#include <cuda_runtime.h>
#include <cuda_fp16.h>
#include <math.h>
#include <stdint.h>

#define D_MODEL 1024
#define NHEAD   16
#define HEAD_DIM 64
#define D_FF    4096
#define BATCH   2
#define SEQ     2048
#define MROWS   (BATCH * SEQ)   // 4096
#define LN_EPS  1e-5f

// ---------------------------------------------------------------------------
// Scratch (device globals)
// ---------------------------------------------------------------------------
__device__ __half g_nx  [MROWS * D_MODEL];
__device__ __half g_q   [MROWS * D_MODEL];   // [B*H, L, 64]
__device__ __half g_k   [MROWS * D_MODEL];
__device__ __half g_v   [MROWS * D_MODEL];
__device__ __half g_attn[MROWS * D_MODEL];   // [B, L, D]
__device__ float  g_x1  [MROWS * D_MODEL];
__device__ __half g_nx2 [MROWS * D_MODEL];
__device__ __half g_ffh [MROWS * D_FF];
__device__ __half g_wqt [D_MODEL * D_MODEL]; // [N][K]
__device__ __half g_wkt [D_MODEL * D_MODEL];
__device__ __half g_wvt [D_MODEL * D_MODEL];
__device__ __half g_wot [D_MODEL * D_MODEL];
__device__ __half g_w1t [D_MODEL * D_FF];
__device__ __half g_w2t [D_MODEL * D_FF];

// ---------------------------------------------------------------------------
// Helpers
// ---------------------------------------------------------------------------
__device__ __forceinline__ uint32_t smem_u32(const void* p) {
    uint32_t a;
    asm("{ .reg .u64 t; cvta.to.shared.u64 t, %1; cvt.u32.u64 %0, t; }" : "=r"(a) : "l"(p));
    return a;
}
__device__ __forceinline__ uint32_t pack_f2h2(float lo, float hi) {
    uint32_t r;
    asm("cvt.rn.f16x2.f32 %0, %1, %2;" : "=r"(r) : "f"(hi), "f"(lo));
    return r;
}
__device__ __forceinline__ float gelu_exact(float v) {
    return 0.5f * v * (1.0f + erff(v * 0.70710678118654752f));
}

#define CP_ASYNC(dst, src) \
    asm volatile("cp.async.cg.shared.global [%0], [%1], 16;" :: "r"(dst), "l"(src))
#define CP_COMMIT() asm volatile("cp.async.commit_group;")
#define CP_WAIT1()  asm volatile("cp.async.wait_group 1;")
#define CP_WAIT0()  asm volatile("cp.async.wait_group 0;")

#define LDSM4(r, addr) \
    asm volatile("ldmatrix.sync.aligned.m8n8.x4.shared.b16 {%0,%1,%2,%3}, [%4];" \
        : "=r"((r)[0]), "=r"((r)[1]), "=r"((r)[2]), "=r"((r)[3]) : "r"(addr))
#define LDSM4T(r, addr) \
    asm volatile("ldmatrix.sync.aligned.m8n8.x4.trans.shared.b16 {%0,%1,%2,%3}, [%4];" \
        : "=r"((r)[0]), "=r"((r)[1]), "=r"((r)[2]), "=r"((r)[3]) : "r"(addr))

__device__ __forceinline__ void mma_f16(float* c,
    uint32_t a0, uint32_t a1, uint32_t a2, uint32_t a3, uint32_t b0, uint32_t b1)
{
    asm volatile(
        "mma.sync.aligned.m16n8k16.row.col.f32.f16.f16.f32 "
        "{%0,%1,%2,%3}, {%4,%5,%6,%7}, {%8,%9}, {%0,%1,%2,%3};"
        : "+f"(c[0]), "+f"(c[1]), "+f"(c[2]), "+f"(c[3])
        : "r"(a0), "r"(a1), "r"(a2), "r"(a3), "r"(b0), "r"(b1));
}

// ---------------------------------------------------------------------------
// Weight transpose (fp32 [K][N] -> half [N][K])
// ---------------------------------------------------------------------------
__device__ __forceinline__ void transpose_body(const float* __restrict__ in,
                                               __half* __restrict__ out, int K, int N)
{
    __shared__ float tile[64][65];
    int tid = threadIdx.x;
    int tx = tid & 63;
    int tg = tid >> 6;
    int x  = blockIdx.x * 64 + tx;
    int y0 = blockIdx.y * 64;
    #pragma unroll
    for (int i = 0; i < 16; i++) {
        int r = tg * 16 + i;
        tile[r][tx] = in[(size_t)(y0 + r) * N + x];
    }
    __syncthreads();
    int xo  = blockIdx.y * 64 + tx;
    int yo0 = blockIdx.x * 64;
    #pragma unroll
    for (int i = 0; i < 16; i++) {
        int r = tg * 16 + i;
        out[(size_t)(yo0 + r) * K + xo] = __float2half(tile[tx][r]);
    }
}

__global__ void transpose4_kernel(const float* __restrict__ w0, const float* __restrict__ w1,
                                  const float* __restrict__ w2, const float* __restrict__ w3,
                                  __half* __restrict__ o0, __half* __restrict__ o1,
                                  __half* __restrict__ o2, __half* __restrict__ o3)
{
    int z = blockIdx.z;
    const float* in = (z == 0) ? w0 : (z == 1) ? w1 : (z == 2) ? w2 : w3;
    __half* out     = (z == 0) ? o0 : (z == 1) ? o1 : (z == 2) ? o2 : o3;
    transpose_body(in, out, D_MODEL, D_MODEL);
}

__global__ void transpose2_kernel(const float* __restrict__ w1, const float* __restrict__ w2,
                                  __half* __restrict__ o1, __half* __restrict__ o2)
{
    if (blockIdx.z == 0) {
        if (blockIdx.x >= D_FF / 64 || blockIdx.y >= D_MODEL / 64) return;
        transpose_body(w1, o1, D_MODEL, D_FF);
    } else {
        if (blockIdx.x >= D_MODEL / 64 || blockIdx.y >= D_FF / 64) return;
        transpose_body(w2, o2, D_FF, D_MODEL);
    }
}

// ---------------------------------------------------------------------------
// LayerNorm: warp-per-row, fp32 in, half out. Block 256 = 8 rows.
// ---------------------------------------------------------------------------
__global__ void ln_kernel(const float* __restrict__ x, const float* __restrict__ g,
                          const float* __restrict__ b, __half* __restrict__ out)
{
    int wid  = threadIdx.x >> 5, lane = threadIdx.x & 31;
    int row  = blockIdx.x * 8 + wid;
    const float4* xr = (const float4*)(x + (size_t)row * D_MODEL);

    float4 v[8];
    float s = 0.f, ss = 0.f;
    #pragma unroll
    for (int i = 0; i < 8; i++) {
        v[i] = xr[i * 32 + lane];
        s  += v[i].x + v[i].y + v[i].z + v[i].w;
        ss += v[i].x*v[i].x + v[i].y*v[i].y + v[i].z*v[i].z + v[i].w*v[i].w;
    }
    #pragma unroll
    for (int o = 16; o > 0; o >>= 1) {
        s  += __shfl_xor_sync(0xffffffffu, s,  o);
        ss += __shfl_xor_sync(0xffffffffu, ss, o);
    }
    float mu   = s  * (1.0f / D_MODEL);
    float var  = ss * (1.0f / D_MODEL) - mu * mu;
    float rstd = rsqrtf(var + LN_EPS);

    const float4* gp = (const float4*)g;
    const float4* bp = (const float4*)b;
    __half* orow = out + (size_t)row * D_MODEL;
    #pragma unroll
    for (int i = 0; i < 8; i++) {
        int idx = i * 32 + lane;
        float4 gv = gp[idx];
        float4 bv = bp[idx];
        uint2 o2;
        o2.x = pack_f2h2((v[i].x - mu) * rstd * gv.x + bv.x,
                         (v[i].y - mu) * rstd * gv.y + bv.y);
        o2.y = pack_f2h2((v[i].z - mu) * rstd * gv.z + bv.z,
                         (v[i].w - mu) * rstd * gv.w + bv.w);
        *(uint2*)(orow + idx * 4) = o2;
    }
}

// ---------------------------------------------------------------------------
// fp16 mma GEMM: BM=BN=128, BK=32, 8 warps 2x4, warp 64x32, m16n8k16.
// Kld = leading dim (stride); Kext = extent of this block's K-slice.
// ---------------------------------------------------------------------------
#define BM 128
#define BN 128
#define BKh 32
#define LDH 40
#define ASZH (BM * LDH)
#define ASZB (ASZH * 2)
#define STAGEB (2 * ASZB)             // 20480
#define NSTAGE 3
#define GEMM_SMEM (NSTAGE * STAGEB)   // 61440

struct Frag { float c[4][4][4]; };

__device__ __forceinline__ void mma_mainloop(const __half* __restrict__ A,
                                             const __half* __restrict__ WT,
                                             int Kld, int Kext, int row0, int col0,
                                             __half* sm, Frag& F)
{
    int tid  = threadIdx.x;
    int lane = tid & 31, wid = tid >> 5;
    int wm = wid >> 2, wn = wid & 3;
    int rr = lane & 7, mat = lane >> 3;

    uint32_t sbase = smem_u32(sm);

    int r0 = tid >> 2;
    int c8 = tid & 3;
    const __half* gA = A  + (size_t)(row0 + r0) * Kld + c8 * 8;
    const __half* gB = WT + (size_t)(col0 + r0) * Kld + c8 * 8;
    uint32_t stA0 = (uint32_t)((r0)      * LDH + c8 * 8) * 2;
    uint32_t stA1 = (uint32_t)((r0 + 64) * LDH + c8 * 8) * 2;
    uint32_t stB0 = stA0 + ASZB;
    uint32_t stB1 = stA1 + ASZB;

    uint32_t offA[2][4], offB[2][2];
    #pragma unroll
    for (int ks = 0; ks < 2; ks++) {
        #pragma unroll
        for (int mf = 0; mf < 4; mf++) {
            int row = wm * 64 + mf * 16 + rr + ((mat & 1) ? 8 : 0);
            int col = ks * 16 + ((mat & 2) ? 8 : 0);
            offA[ks][mf] = (uint32_t)(row * LDH + col) * 2;
        }
        #pragma unroll
        for (int pr = 0; pr < 2; pr++) {
            int row = wn * 32 + pr * 16 + rr + ((mat & 2) ? 8 : 0);
            int col = ks * 16 + ((mat & 1) ? 8 : 0);
            offB[ks][pr] = (uint32_t)(row * LDH + col) * 2 + ASZB;
        }
    }

    #pragma unroll
    for (int mf = 0; mf < 4; mf++)
        #pragma unroll
        for (int nf = 0; nf < 4; nf++)
            #pragma unroll
            for (int r = 0; r < 4; r++) F.c[mf][nf][r] = 0.f;

    int nk = Kext / BKh;

    #pragma unroll
    for (int s = 0; s < 2; s++) {
        uint32_t sb = sbase + s * STAGEB;
        CP_ASYNC(sb + stA0, gA + (size_t)s * BKh);
        CP_ASYNC(sb + stA1, gA + (size_t)64 * Kld + (size_t)s * BKh);
        CP_ASYNC(sb + stB0, gB + (size_t)s * BKh);
        CP_ASYNC(sb + stB1, gB + (size_t)64 * Kld + (size_t)s * BKh);
        CP_COMMIT();
    }

    uint32_t rdoff = 0, wroff = 2 * STAGEB;
    for (int kt = 0; kt < nk; kt++) {
        if (kt == nk - 1) { CP_WAIT0(); } else { CP_WAIT1(); }
        __syncthreads();

        if (kt + 2 < nk) {
            uint32_t sb = sbase + wroff;
            const __half* a = gA + (size_t)(kt + 2) * BKh;
            const __half* b = gB + (size_t)(kt + 2) * BKh;
            CP_ASYNC(sb + stA0, a);
            CP_ASYNC(sb + stA1, a + (size_t)64 * Kld);
            CP_ASYNC(sb + stB0, b);
            CP_ASYNC(sb + stB1, b + (size_t)64 * Kld);
            CP_COMMIT();
            wroff += STAGEB; if (wroff == NSTAGE * STAGEB) wroff = 0;
        }

        uint32_t sb = sbase + rdoff;
        rdoff += STAGEB; if (rdoff == NSTAGE * STAGEB) rdoff = 0;
        #pragma unroll
        for (int ks = 0; ks < 2; ks++) {
            uint32_t bb0[4], bb1[4];
            LDSM4(bb0, sb + offB[ks][0]);
            LDSM4(bb1, sb + offB[ks][1]);
            #pragma unroll
            for (int mf = 0; mf < 4; mf++) {
                uint32_t aa[4];
                LDSM4(aa, sb + offA[ks][mf]);
                mma_f16(F.c[mf][0], aa[0], aa[1], aa[2], aa[3], bb0[0], bb0[1]);
                mma_f16(F.c[mf][1], aa[0], aa[1], aa[2], aa[3], bb0[2], bb0[3]);
                mma_f16(F.c[mf][2], aa[0], aa[1], aa[2], aa[3], bb1[0], bb1[1]);
                mma_f16(F.c[mf][3], aa[0], aa[1], aa[2], aa[3], bb1[2], bb1[3]);
            }
        }
    }
}

// QKV: gridDim.z selects weight; writes head-permuted half [B*H, L, 64]
__global__ __launch_bounds__(256, 2)
void tc_gemm_qkv(const __half* __restrict__ A,
                 const __half* __restrict__ Wqt, const __half* __restrict__ Wkt,
                 const __half* __restrict__ Wvt,
                 const float* __restrict__ bq, const float* __restrict__ bk,
                 const float* __restrict__ bv,
                 __half* __restrict__ Cq, __half* __restrict__ Ck, __half* __restrict__ Cv)
{
    extern __shared__ __half sm[];
    int z = blockIdx.z;
    const __half* WT  = (z == 0) ? Wqt : (z == 1) ? Wkt : Wvt;
    const float* bias = (z == 0) ? bq  : (z == 1) ? bk  : bv;
    __half* C         = (z == 0) ? Cq  : (z == 1) ? Ck  : Cv;

    int row0 = blockIdx.y * BM;
    int col0 = blockIdx.x * BN;
    Frag F;
    mma_mainloop(A, WT, D_MODEL, D_MODEL, row0, col0, sm, F);

    int lane = threadIdx.x & 31, wid = threadIdx.x >> 5;
    int wm = wid >> 2, wn = wid & 3;
    int group = lane >> 2, tig = lane & 3;

    #pragma unroll
    for (int mf = 0; mf < 4; mf++) {
        #pragma unroll
        for (int nf = 0; nf < 4; nf++) {
            int row = row0 + wm * 64 + mf * 16 + group;
            int col = col0 + wn * 32 + nf * 8 + 2 * tig;
            float2 bv2 = *(const float2*)(bias + col);
            int h = col >> 6, d = col & 63;
            #pragma unroll
            for (int hi = 0; hi < 2; hi++) {
                int r = row + hi * 8;
                int b = r >> 11, l = r & (SEQ - 1);
                __half2 o = __floats2half2_rn(F.c[mf][nf][hi * 2 + 0] + bv2.x,
                                              F.c[mf][nf][hi * 2 + 1] + bv2.y);
                *(__half2*)(C + (((size_t)(b * NHEAD + h) * SEQ) + l) * HEAD_DIM + d) = o;
            }
        }
    }
}

// MODE 1: half out = gelu(acc+bias).  MODE 2: float out = res + acc + bias.
template<int MODE>
__global__ __launch_bounds__(256, 2)
void tc_gemm(const __half* __restrict__ A, const __half* __restrict__ WT,
             const float* __restrict__ bias, const float* __restrict__ res,
             void* __restrict__ Cv, int N, int K)
{
    extern __shared__ __half sm[];
    int row0 = blockIdx.y * BM;
    int col0 = blockIdx.x * BN;
    Frag F;
    mma_mainloop(A, WT, K, K, row0, col0, sm, F);

    int lane = threadIdx.x & 31, wid = threadIdx.x >> 5;
    int wm = wid >> 2, wn = wid & 3;
    int group = lane >> 2, tig = lane & 3;

    #pragma unroll
    for (int mf = 0; mf < 4; mf++) {
        #pragma unroll
        for (int nf = 0; nf < 4; nf++) {
            int row = row0 + wm * 64 + mf * 16 + group;
            int col = col0 + wn * 32 + nf * 8 + 2 * tig;
            float2 bv2 = *(const float2*)(bias + col);
            #pragma unroll
            for (int hi = 0; hi < 2; hi++) {
                int r = row + hi * 8;
                float ox = F.c[mf][nf][hi * 2 + 0] + bv2.x;
                float oy = F.c[mf][nf][hi * 2 + 1] + bv2.y;
                if (MODE == 1) {
                    __half2 o = __floats2half2_rn(gelu_exact(ox), gelu_exact(oy));
                    *(__half2*)((__half*)Cv + (size_t)r * N + col) = o;
                } else {
                    float2 r2 = *(const float2*)(res + (size_t)r * N + col);
                    float2 o; o.x = ox + r2.x; o.y = oy + r2.y;
                    *(float2*)((float*)Cv + (size_t)r * N + col) = o;
                }
            }
        }
    }
}

// Split-K (x2) GEMM with atomic-add reduction into zero-initialized C.
// kz=0 contributes acc + bias + res; kz=1 contributes acc only.
// Deterministic: exactly two commutative fp32 adds per element onto 0.
__global__ __launch_bounds__(256, 2)
void tc_gemm_splitk(const __half* __restrict__ A, const __half* __restrict__ WT,
                    const float* __restrict__ bias, const float* __restrict__ res,
                    float* __restrict__ C, int N, int K)
{
    extern __shared__ __half sm[];
    int kz = blockIdx.z;
    int Khalf = K >> 1;
    int row0 = blockIdx.y * BM;
    int col0 = blockIdx.x * BN;
    Frag F;
    mma_mainloop(A + (size_t)kz * Khalf, WT + (size_t)kz * Khalf,
                 K, Khalf, row0, col0, sm, F);

    int lane = threadIdx.x & 31, wid = threadIdx.x >> 5;
    int wm = wid >> 2, wn = wid & 3;
    int group = lane >> 2, tig = lane & 3;

    #pragma unroll
    for (int mf = 0; mf < 4; mf++) {
        #pragma unroll
        for (int nf = 0; nf < 4; nf++) {
            int row = row0 + wm * 64 + mf * 16 + group;
            int col = col0 + wn * 32 + nf * 8 + 2 * tig;
            #pragma unroll
            for (int hi = 0; hi < 2; hi++) {
                int r = row + hi * 8;
                float ox = F.c[mf][nf][hi * 2 + 0];
                float oy = F.c[mf][nf][hi * 2 + 1];
                if (kz == 0) {
                    float2 bv2 = *(const float2*)(bias + col);
                    float2 r2  = *(const float2*)(res + (size_t)r * N + col);
                    ox += bv2.x + r2.x;
                    oy += bv2.y + r2.y;
                }
                atomicAdd(&C[(size_t)r * N + col],     ox);
                atomicAdd(&C[(size_t)r * N + col + 1], oy);
            }
        }
    }
}

// ---------------------------------------------------------------------------
// fp16 mma flash attention (causal). 128 q rows/block, 8 warps, 64-key tiles.
// Heavy q-tiles scheduled first (reversed blockIdx.x).
// ---------------------------------------------------------------------------
__global__ __launch_bounds__(256)
void attn_kernel(const __half* __restrict__ Q, const __half* __restrict__ K,
                 const __half* __restrict__ V, __half* __restrict__ out)
{
    __shared__ __half Qs[128][72];
    __shared__ __half Ks[64][72];
    __shared__ __half Vs[64][72];   // natural [key][d]

    int tid = threadIdx.x;
    int lane = tid & 31, wid = tid >> 5;
    int group = lane >> 2, tig = lane & 3;
    int rr = lane & 7, mat = lane >> 3;
    int qb = (gridDim.x - 1 - blockIdx.x) * 128;   // heavy tiles first
    int bh = blockIdx.y;
    int wb = wid * 16;

    const __half* Qb = Q + (size_t)bh * SEQ * HEAD_DIM;
    const __half* Kb = K + (size_t)bh * SEQ * HEAD_DIM;
    const __half* Vb = V + (size_t)bh * SEQ * HEAD_DIM;

    #pragma unroll
    for (int i = 0; i < 4; i++) {
        int e = tid + i * 256;
        int r = e >> 3, c = e & 7;
        *(uint4*)&Qs[r][c * 8] = *(const uint4*)(Qb + (size_t)(qb + r) * HEAD_DIM + c * 8);
    }
    __syncthreads();

    uint32_t qa[4][4];
    #pragma unroll
    for (int ks = 0; ks < 4; ks++) {
        int kb = ks * 16 + 2 * tig;
        qa[ks][0] = *(const uint32_t*)&Qs[wb + group][kb];
        qa[ks][1] = *(const uint32_t*)&Qs[wb + group + 8][kb];
        qa[ks][2] = *(const uint32_t*)&Qs[wb + group][kb + 8];
        qa[ks][3] = *(const uint32_t*)&Qs[wb + group + 8][kb + 8];
    }

    uint32_t offK[4], offV[4];
    #pragma unroll
    for (int p = 0; p < 4; p++) {
        offK[p] = smem_u32(&Ks[p * 16 + rr + ((mat & 2) ? 8 : 0)][(mat & 1) ? 8 : 0]);
        offV[p] = smem_u32(&Vs[rr + ((mat & 1) ? 8 : 0)][p * 16 + ((mat & 2) ? 8 : 0)]);
    }

    float o[8][4];
    #pragma unroll
    for (int i = 0; i < 8; i++)
        #pragma unroll
        for (int j = 0; j < 4; j++) o[i][j] = 0.f;
    float m2[2] = {-1e30f, -1e30f};
    float l2[2] = {0.f, 0.f};

    const float scale = 0.125f;
    int row_g0 = qb + wb + group;
    int nkt = (qb >> 6) + 2;

    for (int kt = 0; kt < nkt; kt++) {
        __syncthreads();
        #pragma unroll
        for (int i = 0; i < 2; i++) {
            int e = tid + i * 256;
            int r = e >> 3, c = e & 7;
            *(uint4*)&Ks[r][c * 8] = *(const uint4*)(Kb + (size_t)(kt * 64 + r) * HEAD_DIM + c * 8);
            *(uint4*)&Vs[r][c * 8] = *(const uint4*)(Vb + (size_t)(kt * 64 + r) * HEAD_DIM + c * 8);
        }
        __syncthreads();

        bool active = (kt * 64) <= (qb + wb + 15);
        if (active) {
            float s[8][4];
            #pragma unroll
            for (int nf = 0; nf < 8; nf++)
                #pragma unroll
                for (int c = 0; c < 4; c++) s[nf][c] = 0.f;
            #pragma unroll
            for (int ks = 0; ks < 4; ks++) {
                #pragma unroll
                for (int p = 0; p < 4; p++) {
                    uint32_t kb4[4];
                    LDSM4(kb4, offK[p] + ks * 32);
                    mma_f16(s[2*p],   qa[ks][0], qa[ks][1], qa[ks][2], qa[ks][3], kb4[0], kb4[1]);
                    mma_f16(s[2*p+1], qa[ks][0], qa[ks][1], qa[ks][2], qa[ks][3], kb4[2], kb4[3]);
                }
            }

            bool need_mask = (kt * 64 + 63) > (qb + wb);
            #pragma unroll
            for (int nf = 0; nf < 8; nf++) {
                #pragma unroll
                for (int c = 0; c < 4; c++) {
                    float v = s[nf][c] * scale;
                    if (need_mask) {
                        int key = kt * 64 + nf * 8 + 2 * tig + (c & 1);
                        int rg  = row_g0 + ((c >= 2) ? 8 : 0);
                        if (key > rg) v = -1e30f;
                    }
                    s[nf][c] = v;
                }
            }

            #pragma unroll
            for (int r = 0; r < 2; r++) {
                float mx = -1e30f;
                #pragma unroll
                for (int nf = 0; nf < 8; nf++)
                    mx = fmaxf(mx, fmaxf(s[nf][2 * r], s[nf][2 * r + 1]));
                mx = fmaxf(mx, __shfl_xor_sync(0xffffffffu, mx, 1));
                mx = fmaxf(mx, __shfl_xor_sync(0xffffffffu, mx, 2));
                float mnew = fmaxf(m2[r], mx);
                float corr = __expf(m2[r] - mnew);
                float rsum = 0.f;
                #pragma unroll
                for (int nf = 0; nf < 8; nf++) {
                    float p0 = __expf(s[nf][2 * r]     - mnew);
                    float p1 = __expf(s[nf][2 * r + 1] - mnew);
                    s[nf][2 * r] = p0; s[nf][2 * r + 1] = p1;
                    rsum += p0 + p1;
                }
                rsum += __shfl_xor_sync(0xffffffffu, rsum, 1);
                rsum += __shfl_xor_sync(0xffffffffu, rsum, 2);
                l2[r] = l2[r] * corr + rsum;
                m2[r] = mnew;
                #pragma unroll
                for (int nfd = 0; nfd < 8; nfd++) {
                    o[nfd][2 * r]     *= corr;
                    o[nfd][2 * r + 1] *= corr;
                }
            }

            #pragma unroll
            for (int ks = 0; ks < 4; ks++) {
                uint32_t pa0 = pack_f2h2(s[2*ks][0],   s[2*ks][1]);
                uint32_t pa1 = pack_f2h2(s[2*ks][2],   s[2*ks][3]);
                uint32_t pa2 = pack_f2h2(s[2*ks+1][0], s[2*ks+1][1]);
                uint32_t pa3 = pack_f2h2(s[2*ks+1][2], s[2*ks+1][3]);
                #pragma unroll
                for (int p = 0; p < 4; p++) {
                    uint32_t vb4[4];
                    LDSM4T(vb4, offV[p] + ks * (16 * 72 * 2));
                    mma_f16(o[2*p],   pa0, pa1, pa2, pa3, vb4[0], vb4[1]);
                    mma_f16(o[2*p+1], pa0, pa1, pa2, pa3, vb4[2], vb4[3]);
                }
            }
        }
    }

    int b = bh >> 4, h = bh & 15;
    float inv0 = 1.0f / l2[0];
    float inv1 = 1.0f / l2[1];
    #pragma unroll
    for (int r = 0; r < 2; r++) {
        int rg = row_g0 + r * 8;
        int l = rg & (SEQ - 1);
        float inv = r ? inv1 : inv0;
        #pragma unroll
        for (int nfd = 0; nfd < 8; nfd++) {
            int d = nfd * 8 + 2 * tig;
            __half2 ov = __floats2half2_rn(o[nfd][2 * r] * inv, o[nfd][2 * r + 1] * inv);
            *(__half2*)(out + ((size_t)(b * SEQ + l)) * D_MODEL + h * HEAD_DIM + d) = ov;
        }
    }
}

// ---------------------------------------------------------------------------
// Launch
// ---------------------------------------------------------------------------
extern "C" void kernel_launch(void* const* d_in, const int* in_sizes, int n_in,
                              void* d_out, int out_size)
{
    const float* x   = (const float*)d_in[0];
    const float* Wq  = (const float*)d_in[2];
    const float* bq  = (const float*)d_in[3];
    const float* Wk  = (const float*)d_in[4];
    const float* bk  = (const float*)d_in[5];
    const float* Wv  = (const float*)d_in[6];
    const float* bv  = (const float*)d_in[7];
    const float* Wo  = (const float*)d_in[8];
    const float* bo  = (const float*)d_in[9];
    const float* g1  = (const float*)d_in[10];
    const float* b1  = (const float*)d_in[11];
    const float* g2  = (const float*)d_in[12];
    const float* b2  = (const float*)d_in[13];
    const float* W1  = (const float*)d_in[14];
    const float* bf1 = (const float*)d_in[15];
    const float* W2  = (const float*)d_in[16];
    const float* bf2 = (const float*)d_in[17];
    float* out = (float*)d_out;

    __half *p_nx, *p_q, *p_k, *p_v, *p_attn, *p_nx2, *p_ffh;
    __half *p_wqt, *p_wkt, *p_wvt, *p_wot, *p_w1t, *p_w2t;
    float *p_x1;
    cudaGetSymbolAddress((void**)&p_nx,   g_nx);
    cudaGetSymbolAddress((void**)&p_q,    g_q);
    cudaGetSymbolAddress((void**)&p_k,    g_k);
    cudaGetSymbolAddress((void**)&p_v,    g_v);
    cudaGetSymbolAddress((void**)&p_attn, g_attn);
    cudaGetSymbolAddress((void**)&p_x1,   g_x1);
    cudaGetSymbolAddress((void**)&p_nx2,  g_nx2);
    cudaGetSymbolAddress((void**)&p_ffh,  g_ffh);
    cudaGetSymbolAddress((void**)&p_wqt,  g_wqt);
    cudaGetSymbolAddress((void**)&p_wkt,  g_wkt);
    cudaGetSymbolAddress((void**)&p_wvt,  g_wvt);
    cudaGetSymbolAddress((void**)&p_wot,  g_wot);
    cudaGetSymbolAddress((void**)&p_w1t,  g_w1t);
    cudaGetSymbolAddress((void**)&p_w2t,  g_w2t);

    cudaFuncSetAttribute(tc_gemm_qkv,    cudaFuncAttributeMaxDynamicSharedMemorySize, GEMM_SMEM);
    cudaFuncSetAttribute(tc_gemm<1>,     cudaFuncAttributeMaxDynamicSharedMemorySize, GEMM_SMEM);
    cudaFuncSetAttribute(tc_gemm<2>,     cudaFuncAttributeMaxDynamicSharedMemorySize, GEMM_SMEM);
    cudaFuncSetAttribute(tc_gemm_splitk, cudaFuncAttributeMaxDynamicSharedMemorySize, GEMM_SMEM);

    static cudaStream_t s2 = nullptr;
    static cudaEvent_t evFork = nullptr, evJoin = nullptr;
    if (!s2) {
        cudaStreamCreateWithFlags(&s2, cudaStreamNonBlocking);
        cudaEventCreateWithFlags(&evFork, cudaEventDisableTiming);
        cudaEventCreateWithFlags(&evJoin, cudaEventDisableTiming);
    }

    dim3 t256(256);

    // 0a. QKV/O weight transposes (main stream)
    transpose4_kernel<<<dim3(D_MODEL/64, D_MODEL/64, 4), t256>>>(
        Wq, Wk, Wv, Wo, p_wqt, p_wkt, p_wvt, p_wot);

    // 0b. fork: W1/W2 transposes on side stream
    cudaEventRecord(evFork, 0);
    cudaStreamWaitEvent(s2, evFork, 0);
    transpose2_kernel<<<dim3(D_FF/64, D_FF/64, 2), t256, 0, s2>>>(W1, W2, p_w1t, p_w2t);
    cudaEventRecord(evJoin, s2);

    // 1. nx = LN1(x)
    ln_kernel<<<MROWS / 8, t256>>>(x, g1, b1, p_nx);

    // 2. Q/K/V
    dim3 gQKV(D_MODEL / BN, MROWS / BM, 3);
    tc_gemm_qkv<<<gQKV, t256, GEMM_SMEM>>>(p_nx, p_wqt, p_wkt, p_wvt,
                                           bq, bk, bv, p_q, p_k, p_v);

    // 3. causal flash attention
    dim3 gAttn(SEQ / 128, BATCH * NHEAD);
    attn_kernel<<<gAttn, t256>>>(p_q, p_k, p_v, p_attn);

    // 4. x1 = x + attn @ Wo + bo
    dim3 gD(D_MODEL / BN, MROWS / BM);
    tc_gemm<2><<<gD, t256, GEMM_SMEM>>>(p_attn, p_wot, bo, x, p_x1, D_MODEL, D_MODEL);

    // 5. nx2 = LN2(x1)
    ln_kernel<<<MROWS / 8, t256>>>(p_x1, g2, b2, p_nx2);

    // join: W1/W2 transposes must be done before FFN1
    cudaStreamWaitEvent(0, evJoin, 0);

    // 6. h = gelu(nx2 @ W1 + bf1)
    dim3 gF1(D_FF / BN, MROWS / BM);
    tc_gemm<1><<<gF1, t256, GEMM_SMEM>>>(p_nx2, p_w1t, bf1, nullptr, p_ffh, D_FF, D_MODEL);

    // 7. out = x1 + h @ W2 + bf2   (split-K x2, atomic reduction into zeroed out)
    cudaMemsetAsync(out, 0, (size_t)MROWS * D_MODEL * sizeof(float), 0);
    dim3 gF2(D_MODEL / BN, MROWS / BM, 2);
    tc_gemm_splitk<<<gF2, t256, GEMM_SMEM>>>(p_ffh, p_w2t, bf2, p_x1, out, D_MODEL, D_FF);
}

// round 14
// speedup vs baseline: 1.0256x; 1.0256x over previous
#include <cuda_runtime.h>
#include <cuda_fp16.h>
#include <math.h>
#include <stdint.h>

#define D_MODEL 1024
#define NHEAD   16
#define HEAD_DIM 64
#define D_FF    4096
#define BATCH   2
#define SEQ     2048
#define MROWS   (BATCH * SEQ)   // 4096
#define LN_EPS  1e-5f

// ---------------------------------------------------------------------------
// Scratch (device globals)
// ---------------------------------------------------------------------------
__device__ __half g_nx  [MROWS * D_MODEL];
__device__ __half g_q   [MROWS * D_MODEL];   // [B*H, L, 64]
__device__ __half g_k   [MROWS * D_MODEL];
__device__ __half g_v   [MROWS * D_MODEL];
__device__ __half g_attn[MROWS * D_MODEL];   // [B, L, D]
__device__ float  g_x1  [MROWS * D_MODEL];
__device__ __half g_nx2 [MROWS * D_MODEL];
__device__ __half g_ffh [MROWS * D_FF];
__device__ __half g_wqt [D_MODEL * D_MODEL]; // [N][K]
__device__ __half g_wkt [D_MODEL * D_MODEL];
__device__ __half g_wvt [D_MODEL * D_MODEL];
__device__ __half g_wot [D_MODEL * D_MODEL];
__device__ __half g_w1t [D_MODEL * D_FF];
__device__ __half g_w2t [D_MODEL * D_FF];

// ---------------------------------------------------------------------------
// Helpers
// ---------------------------------------------------------------------------
__device__ __forceinline__ uint32_t smem_u32(const void* p) {
    uint32_t a;
    asm("{ .reg .u64 t; cvta.to.shared.u64 t, %1; cvt.u32.u64 %0, t; }" : "=r"(a) : "l"(p));
    return a;
}
__device__ __forceinline__ uint32_t pack_f2h2(float lo, float hi) {
    uint32_t r;
    asm("cvt.rn.f16x2.f32 %0, %1, %2;" : "=r"(r) : "f"(hi), "f"(lo));
    return r;
}
__device__ __forceinline__ float gelu_exact(float v) {
    return 0.5f * v * (1.0f + erff(v * 0.70710678118654752f));
}

#define CP_ASYNC(dst, src) \
    asm volatile("cp.async.cg.shared.global [%0], [%1], 16;" :: "r"(dst), "l"(src))
#define CP_COMMIT() asm volatile("cp.async.commit_group;")
#define CP_WAIT1()  asm volatile("cp.async.wait_group 1;")
#define CP_WAIT0()  asm volatile("cp.async.wait_group 0;")

#define LDSM4(r, addr) \
    asm volatile("ldmatrix.sync.aligned.m8n8.x4.shared.b16 {%0,%1,%2,%3}, [%4];" \
        : "=r"((r)[0]), "=r"((r)[1]), "=r"((r)[2]), "=r"((r)[3]) : "r"(addr))
#define LDSM4T(r, addr) \
    asm volatile("ldmatrix.sync.aligned.m8n8.x4.trans.shared.b16 {%0,%1,%2,%3}, [%4];" \
        : "=r"((r)[0]), "=r"((r)[1]), "=r"((r)[2]), "=r"((r)[3]) : "r"(addr))

__device__ __forceinline__ void mma_f16(float* c,
    uint32_t a0, uint32_t a1, uint32_t a2, uint32_t a3, uint32_t b0, uint32_t b1)
{
    asm volatile(
        "mma.sync.aligned.m16n8k16.row.col.f32.f16.f16.f32 "
        "{%0,%1,%2,%3}, {%4,%5,%6,%7}, {%8,%9}, {%0,%1,%2,%3};"
        : "+f"(c[0]), "+f"(c[1]), "+f"(c[2]), "+f"(c[3])
        : "r"(a0), "r"(a1), "r"(a2), "r"(a3), "r"(b0), "r"(b1));
}

// ---------------------------------------------------------------------------
// Weight transpose (fp32 [K][N] -> half [N][K])
// ---------------------------------------------------------------------------
__device__ __forceinline__ void transpose_body(const float* __restrict__ in,
                                               __half* __restrict__ out, int K, int N)
{
    __shared__ float tile[64][65];
    int tid = threadIdx.x;
    int tx = tid & 63;
    int tg = tid >> 6;
    int x  = blockIdx.x * 64 + tx;
    int y0 = blockIdx.y * 64;
    #pragma unroll
    for (int i = 0; i < 16; i++) {
        int r = tg * 16 + i;
        tile[r][tx] = in[(size_t)(y0 + r) * N + x];
    }
    __syncthreads();
    int xo  = blockIdx.y * 64 + tx;
    int yo0 = blockIdx.x * 64;
    #pragma unroll
    for (int i = 0; i < 16; i++) {
        int r = tg * 16 + i;
        out[(size_t)(yo0 + r) * K + xo] = __float2half(tile[tx][r]);
    }
}

__global__ void transpose4_kernel(const float* __restrict__ w0, const float* __restrict__ w1,
                                  const float* __restrict__ w2, const float* __restrict__ w3,
                                  __half* __restrict__ o0, __half* __restrict__ o1,
                                  __half* __restrict__ o2, __half* __restrict__ o3)
{
    int z = blockIdx.z;
    const float* in = (z == 0) ? w0 : (z == 1) ? w1 : (z == 2) ? w2 : w3;
    __half* out     = (z == 0) ? o0 : (z == 1) ? o1 : (z == 2) ? o2 : o3;
    transpose_body(in, out, D_MODEL, D_MODEL);
}

__global__ void transpose2_kernel(const float* __restrict__ w1, const float* __restrict__ w2,
                                  __half* __restrict__ o1, __half* __restrict__ o2)
{
    if (blockIdx.z == 0) {
        if (blockIdx.x >= D_FF / 64 || blockIdx.y >= D_MODEL / 64) return;
        transpose_body(w1, o1, D_MODEL, D_FF);
    } else {
        if (blockIdx.x >= D_MODEL / 64 || blockIdx.y >= D_FF / 64) return;
        transpose_body(w2, o2, D_FF, D_MODEL);
    }
}

// ---------------------------------------------------------------------------
// LayerNorm: warp-per-row, fp32 in, half out. Block 256 = 8 rows.
// ---------------------------------------------------------------------------
__global__ void ln_kernel(const float* __restrict__ x, const float* __restrict__ g,
                          const float* __restrict__ b, __half* __restrict__ out)
{
    int wid  = threadIdx.x >> 5, lane = threadIdx.x & 31;
    int row  = blockIdx.x * 8 + wid;
    const float4* xr = (const float4*)(x + (size_t)row * D_MODEL);

    float4 v[8];
    float s = 0.f, ss = 0.f;
    #pragma unroll
    for (int i = 0; i < 8; i++) {
        v[i] = xr[i * 32 + lane];
        s  += v[i].x + v[i].y + v[i].z + v[i].w;
        ss += v[i].x*v[i].x + v[i].y*v[i].y + v[i].z*v[i].z + v[i].w*v[i].w;
    }
    #pragma unroll
    for (int o = 16; o > 0; o >>= 1) {
        s  += __shfl_xor_sync(0xffffffffu, s,  o);
        ss += __shfl_xor_sync(0xffffffffu, ss, o);
    }
    float mu   = s  * (1.0f / D_MODEL);
    float var  = ss * (1.0f / D_MODEL) - mu * mu;
    float rstd = rsqrtf(var + LN_EPS);

    const float4* gp = (const float4*)g;
    const float4* bp = (const float4*)b;
    __half* orow = out + (size_t)row * D_MODEL;
    #pragma unroll
    for (int i = 0; i < 8; i++) {
        int idx = i * 32 + lane;
        float4 gv = gp[idx];
        float4 bv = bp[idx];
        uint2 o2;
        o2.x = pack_f2h2((v[i].x - mu) * rstd * gv.x + bv.x,
                         (v[i].y - mu) * rstd * gv.y + bv.y);
        o2.y = pack_f2h2((v[i].z - mu) * rstd * gv.z + bv.z,
                         (v[i].w - mu) * rstd * gv.w + bv.w);
        *(uint2*)(orow + idx * 4) = o2;
    }
}

// ---------------------------------------------------------------------------
// fp16 mma GEMM: BM=BN=128, BK=32, 8 warps 2x4, warp 64x32, m16n8k16.
// ldmatrix fragments, 3-stage cp.async, 2 CTAs/SM.
// ---------------------------------------------------------------------------
#define BM 128
#define BN 128
#define BKh 32
#define LDH 40
#define ASZH (BM * LDH)
#define ASZB (ASZH * 2)
#define STAGEB (2 * ASZB)             // 20480
#define NSTAGE 3
#define GEMM_SMEM (NSTAGE * STAGEB)   // 61440

struct Frag { float c[4][4][4]; };

__device__ __forceinline__ void mma_mainloop(const __half* __restrict__ A,
                                             const __half* __restrict__ WT,
                                             int K, int row0, int col0,
                                             __half* sm, Frag& F)
{
    int tid  = threadIdx.x;
    int lane = tid & 31, wid = tid >> 5;
    int wm = wid >> 2, wn = wid & 3;
    int rr = lane & 7, mat = lane >> 3;

    uint32_t sbase = smem_u32(sm);

    int r0 = tid >> 2;
    int c8 = tid & 3;
    const __half* gA = A  + (size_t)(row0 + r0) * K + c8 * 8;
    const __half* gB = WT + (size_t)(col0 + r0) * K + c8 * 8;
    uint32_t stA0 = (uint32_t)((r0)      * LDH + c8 * 8) * 2;
    uint32_t stA1 = (uint32_t)((r0 + 64) * LDH + c8 * 8) * 2;
    uint32_t stB0 = stA0 + ASZB;
    uint32_t stB1 = stA1 + ASZB;

    uint32_t offA[2][4], offB[2][2];
    #pragma unroll
    for (int ks = 0; ks < 2; ks++) {
        #pragma unroll
        for (int mf = 0; mf < 4; mf++) {
            int row = wm * 64 + mf * 16 + rr + ((mat & 1) ? 8 : 0);
            int col = ks * 16 + ((mat & 2) ? 8 : 0);
            offA[ks][mf] = (uint32_t)(row * LDH + col) * 2;
        }
        #pragma unroll
        for (int pr = 0; pr < 2; pr++) {
            int row = wn * 32 + pr * 16 + rr + ((mat & 2) ? 8 : 0);
            int col = ks * 16 + ((mat & 1) ? 8 : 0);
            offB[ks][pr] = (uint32_t)(row * LDH + col) * 2 + ASZB;
        }
    }

    #pragma unroll
    for (int mf = 0; mf < 4; mf++)
        #pragma unroll
        for (int nf = 0; nf < 4; nf++)
            #pragma unroll
            for (int r = 0; r < 4; r++) F.c[mf][nf][r] = 0.f;

    int nk = K / BKh;

    #pragma unroll
    for (int s = 0; s < 2; s++) {
        uint32_t sb = sbase + s * STAGEB;
        CP_ASYNC(sb + stA0, gA + (size_t)s * BKh);
        CP_ASYNC(sb + stA1, gA + (size_t)64 * K + (size_t)s * BKh);
        CP_ASYNC(sb + stB0, gB + (size_t)s * BKh);
        CP_ASYNC(sb + stB1, gB + (size_t)64 * K + (size_t)s * BKh);
        CP_COMMIT();
    }

    uint32_t rdoff = 0, wroff = 2 * STAGEB;
    for (int kt = 0; kt < nk; kt++) {
        if (kt == nk - 1) { CP_WAIT0(); } else { CP_WAIT1(); }
        __syncthreads();

        if (kt + 2 < nk) {
            uint32_t sb = sbase + wroff;
            const __half* a = gA + (size_t)(kt + 2) * BKh;
            const __half* b = gB + (size_t)(kt + 2) * BKh;
            CP_ASYNC(sb + stA0, a);
            CP_ASYNC(sb + stA1, a + (size_t)64 * K);
            CP_ASYNC(sb + stB0, b);
            CP_ASYNC(sb + stB1, b + (size_t)64 * K);
            CP_COMMIT();
            wroff += STAGEB; if (wroff == NSTAGE * STAGEB) wroff = 0;
        }

        uint32_t sb = sbase + rdoff;
        rdoff += STAGEB; if (rdoff == NSTAGE * STAGEB) rdoff = 0;
        #pragma unroll
        for (int ks = 0; ks < 2; ks++) {
            uint32_t bb0[4], bb1[4];
            LDSM4(bb0, sb + offB[ks][0]);
            LDSM4(bb1, sb + offB[ks][1]);
            #pragma unroll
            for (int mf = 0; mf < 4; mf++) {
                uint32_t aa[4];
                LDSM4(aa, sb + offA[ks][mf]);
                mma_f16(F.c[mf][0], aa[0], aa[1], aa[2], aa[3], bb0[0], bb0[1]);
                mma_f16(F.c[mf][1], aa[0], aa[1], aa[2], aa[3], bb0[2], bb0[3]);
                mma_f16(F.c[mf][2], aa[0], aa[1], aa[2], aa[3], bb1[0], bb1[1]);
                mma_f16(F.c[mf][3], aa[0], aa[1], aa[2], aa[3], bb1[2], bb1[3]);
            }
        }
    }
}

// QKV: gridDim.z selects weight; writes head-permuted half [B*H, L, 64]
__global__ __launch_bounds__(256, 2)
void tc_gemm_qkv(const __half* __restrict__ A,
                 const __half* __restrict__ Wqt, const __half* __restrict__ Wkt,
                 const __half* __restrict__ Wvt,
                 const float* __restrict__ bq, const float* __restrict__ bk,
                 const float* __restrict__ bv,
                 __half* __restrict__ Cq, __half* __restrict__ Ck, __half* __restrict__ Cv)
{
    extern __shared__ __half sm[];
    int z = blockIdx.z;
    const __half* WT  = (z == 0) ? Wqt : (z == 1) ? Wkt : Wvt;
    const float* bias = (z == 0) ? bq  : (z == 1) ? bk  : bv;
    __half* C         = (z == 0) ? Cq  : (z == 1) ? Ck  : Cv;

    int row0 = blockIdx.y * BM;
    int col0 = blockIdx.x * BN;
    Frag F;
    mma_mainloop(A, WT, D_MODEL, row0, col0, sm, F);

    int lane = threadIdx.x & 31, wid = threadIdx.x >> 5;
    int wm = wid >> 2, wn = wid & 3;
    int group = lane >> 2, tig = lane & 3;

    #pragma unroll
    for (int mf = 0; mf < 4; mf++) {
        #pragma unroll
        for (int nf = 0; nf < 4; nf++) {
            int row = row0 + wm * 64 + mf * 16 + group;
            int col = col0 + wn * 32 + nf * 8 + 2 * tig;
            float2 bv2 = *(const float2*)(bias + col);
            int h = col >> 6, d = col & 63;
            #pragma unroll
            for (int hi = 0; hi < 2; hi++) {
                int r = row + hi * 8;
                int b = r >> 11, l = r & (SEQ - 1);
                __half2 o = __floats2half2_rn(F.c[mf][nf][hi * 2 + 0] + bv2.x,
                                              F.c[mf][nf][hi * 2 + 1] + bv2.y);
                *(__half2*)(C + (((size_t)(b * NHEAD + h) * SEQ) + l) * HEAD_DIM + d) = o;
            }
        }
    }
}

// MODE 1: half out = gelu(acc+bias).  MODE 2: float out = res + acc + bias.
template<int MODE>
__global__ __launch_bounds__(256, 2)
void tc_gemm(const __half* __restrict__ A, const __half* __restrict__ WT,
             const float* __restrict__ bias, const float* __restrict__ res,
             void* __restrict__ Cv, int N, int K)
{
    extern __shared__ __half sm[];
    int row0 = blockIdx.y * BM;
    int col0 = blockIdx.x * BN;
    Frag F;
    mma_mainloop(A, WT, K, row0, col0, sm, F);

    int lane = threadIdx.x & 31, wid = threadIdx.x >> 5;
    int wm = wid >> 2, wn = wid & 3;
    int group = lane >> 2, tig = lane & 3;

    #pragma unroll
    for (int mf = 0; mf < 4; mf++) {
        #pragma unroll
        for (int nf = 0; nf < 4; nf++) {
            int row = row0 + wm * 64 + mf * 16 + group;
            int col = col0 + wn * 32 + nf * 8 + 2 * tig;
            float2 bv2 = *(const float2*)(bias + col);
            #pragma unroll
            for (int hi = 0; hi < 2; hi++) {
                int r = row + hi * 8;
                float ox = F.c[mf][nf][hi * 2 + 0] + bv2.x;
                float oy = F.c[mf][nf][hi * 2 + 1] + bv2.y;
                if (MODE == 1) {
                    __half2 o = __floats2half2_rn(gelu_exact(ox), gelu_exact(oy));
                    *(__half2*)((__half*)Cv + (size_t)r * N + col) = o;
                } else {
                    float2 r2 = *(const float2*)(res + (size_t)r * N + col);
                    float2 o; o.x = ox + r2.x; o.y = oy + r2.y;
                    *(float2*)((float*)Cv + (size_t)r * N + col) = o;
                }
            }
        }
    }
}

// ---------------------------------------------------------------------------
// fp16 mma flash attention (causal). 128 q rows/block, 8 warps, 64-key tiles.
// K/V double-buffered via cp.async; heavy q-tiles scheduled first.
// ---------------------------------------------------------------------------
__global__ __launch_bounds__(256)
void attn_kernel(const __half* __restrict__ Q, const __half* __restrict__ K,
                 const __half* __restrict__ V, __half* __restrict__ out)
{
    __shared__ __half Qs[128][72];
    __shared__ __half KV[2][2][64][72];   // [buf][k/v][row][col]

    int tid = threadIdx.x;
    int lane = tid & 31, wid = tid >> 5;
    int group = lane >> 2, tig = lane & 3;
    int rr = lane & 7, mat = lane >> 3;
    int qb = (gridDim.x - 1 - blockIdx.x) * 128;   // heavy tiles first
    int bh = blockIdx.y;
    int wb = wid * 16;

    const __half* Qb = Q + (size_t)bh * SEQ * HEAD_DIM;
    const __half* Kb = K + (size_t)bh * SEQ * HEAD_DIM;
    const __half* Vb = V + (size_t)bh * SEQ * HEAD_DIM;

    #pragma unroll
    for (int i = 0; i < 4; i++) {
        int e = tid + i * 256;
        int r = e >> 3, c = e & 7;
        *(uint4*)&Qs[r][c * 8] = *(const uint4*)(Qb + (size_t)(qb + r) * HEAD_DIM + c * 8);
    }

    // cp.async staging addresses: 2 chunks/thread for K, 2 for V, per buffer
    int lr[2], lc[2];
    uint32_t dK[2][2], dV[2][2];
    #pragma unroll
    for (int i = 0; i < 2; i++) {
        int e = tid + i * 256;
        lr[i] = e >> 3; lc[i] = (e & 7) * 8;
        #pragma unroll
        for (int buf = 0; buf < 2; buf++) {
            dK[buf][i] = smem_u32(&KV[buf][0][lr[i]][lc[i]]);
            dV[buf][i] = smem_u32(&KV[buf][1][lr[i]][lc[i]]);
        }
    }

    int nkt = (qb >> 6) + 2;

    // prologue: stage tile 0 into buf 0
    #pragma unroll
    for (int i = 0; i < 2; i++) {
        CP_ASYNC(dK[0][i], Kb + (size_t)lr[i] * HEAD_DIM + lc[i]);
        CP_ASYNC(dV[0][i], Vb + (size_t)lr[i] * HEAD_DIM + lc[i]);
    }
    CP_COMMIT();

    __syncthreads();   // Qs visible

    uint32_t qa[4][4];
    #pragma unroll
    for (int ks = 0; ks < 4; ks++) {
        int kb = ks * 16 + 2 * tig;
        qa[ks][0] = *(const uint32_t*)&Qs[wb + group][kb];
        qa[ks][1] = *(const uint32_t*)&Qs[wb + group + 8][kb];
        qa[ks][2] = *(const uint32_t*)&Qs[wb + group][kb + 8];
        qa[ks][3] = *(const uint32_t*)&Qs[wb + group + 8][kb + 8];
    }

    uint32_t offK[4], offV[4];
    #pragma unroll
    for (int p = 0; p < 4; p++) {
        offK[p] = smem_u32(&KV[0][0][p * 16 + rr + ((mat & 2) ? 8 : 0)][(mat & 1) ? 8 : 0]);
        offV[p] = smem_u32(&KV[0][1][rr + ((mat & 1) ? 8 : 0)][p * 16 + ((mat & 2) ? 8 : 0)]);
    }
    const uint32_t BUFB = (uint32_t)sizeof(KV[0]);   // 18432 bytes

    float o[8][4];
    #pragma unroll
    for (int i = 0; i < 8; i++)
        #pragma unroll
        for (int j = 0; j < 4; j++) o[i][j] = 0.f;
    float m2[2] = {-1e30f, -1e30f};
    float l2[2] = {0.f, 0.f};

    const float scale = 0.125f;
    int row_g0 = qb + wb + group;

    for (int kt = 0; kt < nkt; kt++) {
        __syncthreads();   // all readers of buf (kt+1)&1 (iter kt-1) are done

        if (kt + 1 < nkt) {
            int nb = (kt + 1) & 1;
            const __half* kp = Kb + (size_t)(kt + 1) * 64 * HEAD_DIM;
            const __half* vp = Vb + (size_t)(kt + 1) * 64 * HEAD_DIM;
            #pragma unroll
            for (int i = 0; i < 2; i++) {
                CP_ASYNC(dK[nb][i], kp + (size_t)lr[i] * HEAD_DIM + lc[i]);
                CP_ASYNC(dV[nb][i], vp + (size_t)lr[i] * HEAD_DIM + lc[i]);
            }
            CP_COMMIT();
            CP_WAIT1();
        } else {
            CP_WAIT0();
        }
        __syncthreads();   // buf kt&1 contents visible to all

        uint32_t bsel = (kt & 1) ? BUFB : 0;

        bool active = (kt * 64) <= (qb + wb + 15);
        if (active) {
            float s[8][4];
            #pragma unroll
            for (int nf = 0; nf < 8; nf++)
                #pragma unroll
                for (int c = 0; c < 4; c++) s[nf][c] = 0.f;
            #pragma unroll
            for (int ks = 0; ks < 4; ks++) {
                #pragma unroll
                for (int p = 0; p < 4; p++) {
                    uint32_t kb4[4];
                    LDSM4(kb4, offK[p] + bsel + ks * 32);
                    mma_f16(s[2*p],   qa[ks][0], qa[ks][1], qa[ks][2], qa[ks][3], kb4[0], kb4[1]);
                    mma_f16(s[2*p+1], qa[ks][0], qa[ks][1], qa[ks][2], qa[ks][3], kb4[2], kb4[3]);
                }
            }

            bool need_mask = (kt * 64 + 63) > (qb + wb);
            #pragma unroll
            for (int nf = 0; nf < 8; nf++) {
                #pragma unroll
                for (int c = 0; c < 4; c++) {
                    float v = s[nf][c] * scale;
                    if (need_mask) {
                        int key = kt * 64 + nf * 8 + 2 * tig + (c & 1);
                        int rg  = row_g0 + ((c >= 2) ? 8 : 0);
                        if (key > rg) v = -1e30f;
                    }
                    s[nf][c] = v;
                }
            }

            #pragma unroll
            for (int r = 0; r < 2; r++) {
                float mx = -1e30f;
                #pragma unroll
                for (int nf = 0; nf < 8; nf++)
                    mx = fmaxf(mx, fmaxf(s[nf][2 * r], s[nf][2 * r + 1]));
                mx = fmaxf(mx, __shfl_xor_sync(0xffffffffu, mx, 1));
                mx = fmaxf(mx, __shfl_xor_sync(0xffffffffu, mx, 2));
                float mnew = fmaxf(m2[r], mx);
                float corr = __expf(m2[r] - mnew);
                float rsum = 0.f;
                #pragma unroll
                for (int nf = 0; nf < 8; nf++) {
                    float p0 = __expf(s[nf][2 * r]     - mnew);
                    float p1 = __expf(s[nf][2 * r + 1] - mnew);
                    s[nf][2 * r] = p0; s[nf][2 * r + 1] = p1;
                    rsum += p0 + p1;
                }
                rsum += __shfl_xor_sync(0xffffffffu, rsum, 1);
                rsum += __shfl_xor_sync(0xffffffffu, rsum, 2);
                l2[r] = l2[r] * corr + rsum;
                m2[r] = mnew;
                #pragma unroll
                for (int nfd = 0; nfd < 8; nfd++) {
                    o[nfd][2 * r]     *= corr;
                    o[nfd][2 * r + 1] *= corr;
                }
            }

            #pragma unroll
            for (int ks = 0; ks < 4; ks++) {
                uint32_t pa0 = pack_f2h2(s[2*ks][0],   s[2*ks][1]);
                uint32_t pa1 = pack_f2h2(s[2*ks][2],   s[2*ks][3]);
                uint32_t pa2 = pack_f2h2(s[2*ks+1][0], s[2*ks+1][1]);
                uint32_t pa3 = pack_f2h2(s[2*ks+1][2], s[2*ks+1][3]);
                #pragma unroll
                for (int p = 0; p < 4; p++) {
                    uint32_t vb4[4];
                    LDSM4T(vb4, offV[p] + bsel + ks * (16 * 72 * 2));
                    mma_f16(o[2*p],   pa0, pa1, pa2, pa3, vb4[0], vb4[1]);
                    mma_f16(o[2*p+1], pa0, pa1, pa2, pa3, vb4[2], vb4[3]);
                }
            }
        }
    }

    int b = bh >> 4, h = bh & 15;
    float inv0 = 1.0f / l2[0];
    float inv1 = 1.0f / l2[1];
    #pragma unroll
    for (int r = 0; r < 2; r++) {
        int rg = row_g0 + r * 8;
        int l = rg & (SEQ - 1);
        float inv = r ? inv1 : inv0;
        #pragma unroll
        for (int nfd = 0; nfd < 8; nfd++) {
            int d = nfd * 8 + 2 * tig;
            __half2 ov = __floats2half2_rn(o[nfd][2 * r] * inv, o[nfd][2 * r + 1] * inv);
            *(__half2*)(out + ((size_t)(b * SEQ + l)) * D_MODEL + h * HEAD_DIM + d) = ov;
        }
    }
}

// ---------------------------------------------------------------------------
// Launch
// ---------------------------------------------------------------------------
extern "C" void kernel_launch(void* const* d_in, const int* in_sizes, int n_in,
                              void* d_out, int out_size)
{
    const float* x   = (const float*)d_in[0];
    const float* Wq  = (const float*)d_in[2];
    const float* bq  = (const float*)d_in[3];
    const float* Wk  = (const float*)d_in[4];
    const float* bk  = (const float*)d_in[5];
    const float* Wv  = (const float*)d_in[6];
    const float* bv  = (const float*)d_in[7];
    const float* Wo  = (const float*)d_in[8];
    const float* bo  = (const float*)d_in[9];
    const float* g1  = (const float*)d_in[10];
    const float* b1  = (const float*)d_in[11];
    const float* g2  = (const float*)d_in[12];
    const float* b2  = (const float*)d_in[13];
    const float* W1  = (const float*)d_in[14];
    const float* bf1 = (const float*)d_in[15];
    const float* W2  = (const float*)d_in[16];
    const float* bf2 = (const float*)d_in[17];
    float* out = (float*)d_out;

    __half *p_nx, *p_q, *p_k, *p_v, *p_attn, *p_nx2, *p_ffh;
    __half *p_wqt, *p_wkt, *p_wvt, *p_wot, *p_w1t, *p_w2t;
    float *p_x1;
    cudaGetSymbolAddress((void**)&p_nx,   g_nx);
    cudaGetSymbolAddress((void**)&p_q,    g_q);
    cudaGetSymbolAddress((void**)&p_k,    g_k);
    cudaGetSymbolAddress((void**)&p_v,    g_v);
    cudaGetSymbolAddress((void**)&p_attn, g_attn);
    cudaGetSymbolAddress((void**)&p_x1,   g_x1);
    cudaGetSymbolAddress((void**)&p_nx2,  g_nx2);
    cudaGetSymbolAddress((void**)&p_ffh,  g_ffh);
    cudaGetSymbolAddress((void**)&p_wqt,  g_wqt);
    cudaGetSymbolAddress((void**)&p_wkt,  g_wkt);
    cudaGetSymbolAddress((void**)&p_wvt,  g_wvt);
    cudaGetSymbolAddress((void**)&p_wot,  g_wot);
    cudaGetSymbolAddress((void**)&p_w1t,  g_w1t);
    cudaGetSymbolAddress((void**)&p_w2t,  g_w2t);

    cudaFuncSetAttribute(tc_gemm_qkv, cudaFuncAttributeMaxDynamicSharedMemorySize, GEMM_SMEM);
    cudaFuncSetAttribute(tc_gemm<1>,  cudaFuncAttributeMaxDynamicSharedMemorySize, GEMM_SMEM);
    cudaFuncSetAttribute(tc_gemm<2>,  cudaFuncAttributeMaxDynamicSharedMemorySize, GEMM_SMEM);

    static cudaStream_t s2 = nullptr;
    static cudaEvent_t evFork = nullptr, evJoin = nullptr;
    if (!s2) {
        cudaStreamCreateWithFlags(&s2, cudaStreamNonBlocking);
        cudaEventCreateWithFlags(&evFork, cudaEventDisableTiming);
        cudaEventCreateWithFlags(&evJoin, cudaEventDisableTiming);
    }

    dim3 t256(256);

    // 0a. QKV/O weight transposes (main stream)
    transpose4_kernel<<<dim3(D_MODEL/64, D_MODEL/64, 4), t256>>>(
        Wq, Wk, Wv, Wo, p_wqt, p_wkt, p_wvt, p_wot);

    // 0b. fork: W1/W2 transposes on side stream
    cudaEventRecord(evFork, 0);
    cudaStreamWaitEvent(s2, evFork, 0);
    transpose2_kernel<<<dim3(D_FF/64, D_FF/64, 2), t256, 0, s2>>>(W1, W2, p_w1t, p_w2t);
    cudaEventRecord(evJoin, s2);

    // 1. nx = LN1(x)
    ln_kernel<<<MROWS / 8, t256>>>(x, g1, b1, p_nx);

    // 2. Q/K/V
    dim3 gQKV(D_MODEL / BN, MROWS / BM, 3);
    tc_gemm_qkv<<<gQKV, t256, GEMM_SMEM>>>(p_nx, p_wqt, p_wkt, p_wvt,
                                           bq, bk, bv, p_q, p_k, p_v);

    // 3. causal flash attention (K/V double-buffered)
    dim3 gAttn(SEQ / 128, BATCH * NHEAD);
    attn_kernel<<<gAttn, t256>>>(p_q, p_k, p_v, p_attn);

    // 4. x1 = x + attn @ Wo + bo
    dim3 gD(D_MODEL / BN, MROWS / BM);
    tc_gemm<2><<<gD, t256, GEMM_SMEM>>>(p_attn, p_wot, bo, x, p_x1, D_MODEL, D_MODEL);

    // 5. nx2 = LN2(x1)
    ln_kernel<<<MROWS / 8, t256>>>(p_x1, g2, b2, p_nx2);

    // join: W1/W2 transposes must be done before FFN1
    cudaStreamWaitEvent(0, evJoin, 0);

    // 6. h = gelu(nx2 @ W1 + bf1)
    dim3 gF1(D_FF / BN, MROWS / BM);
    tc_gemm<1><<<gF1, t256, GEMM_SMEM>>>(p_nx2, p_w1t, bf1, nullptr, p_ffh, D_FF, D_MODEL);

    // 7. out = x1 + h @ W2 + bf2
    tc_gemm<2><<<gD, t256, GEMM_SMEM>>>(p_ffh, p_w2t, bf2, p_x1, out, D_MODEL, D_FF);
}

// round 15
// speedup vs baseline: 1.0345x; 1.0087x over previous
#include <cuda_runtime.h>
#include <cuda_fp16.h>
#include <math.h>
#include <stdint.h>

#define D_MODEL 1024
#define NHEAD   16
#define HEAD_DIM 64
#define D_FF    4096
#define BATCH   2
#define SEQ     2048
#define MROWS   (BATCH * SEQ)   // 4096
#define LN_EPS  1e-5f

// ---------------------------------------------------------------------------
// Scratch (device globals)
// ---------------------------------------------------------------------------
__device__ __half g_nx  [MROWS * D_MODEL];
__device__ __half g_q   [MROWS * D_MODEL];   // [B*H, L, 64]
__device__ __half g_k   [MROWS * D_MODEL];
__device__ __half g_v   [MROWS * D_MODEL];
__device__ __half g_attn[MROWS * D_MODEL];   // [B, L, D]
__device__ float  g_x1  [MROWS * D_MODEL];
__device__ __half g_nx2 [MROWS * D_MODEL];
__device__ __half g_ffh [MROWS * D_FF];
__device__ __half g_wqt [D_MODEL * D_MODEL]; // [N][K]
__device__ __half g_wkt [D_MODEL * D_MODEL];
__device__ __half g_wvt [D_MODEL * D_MODEL];
__device__ __half g_wot [D_MODEL * D_MODEL];
__device__ __half g_w1t [D_MODEL * D_FF];
__device__ __half g_w2t [D_MODEL * D_FF];

// ---------------------------------------------------------------------------
// Helpers
// ---------------------------------------------------------------------------
__device__ __forceinline__ uint32_t smem_u32(const void* p) {
    uint32_t a;
    asm("{ .reg .u64 t; cvta.to.shared.u64 t, %1; cvt.u32.u64 %0, t; }" : "=r"(a) : "l"(p));
    return a;
}
__device__ __forceinline__ uint32_t pack_f2h2(float lo, float hi) {
    uint32_t r;
    asm("cvt.rn.f16x2.f32 %0, %1, %2;" : "=r"(r) : "f"(hi), "f"(lo));
    return r;
}
__device__ __forceinline__ float gelu_exact(float v) {
    return 0.5f * v * (1.0f + erff(v * 0.70710678118654752f));
}

#define CP_ASYNC(dst, src) \
    asm volatile("cp.async.cg.shared.global [%0], [%1], 16;" :: "r"(dst), "l"(src))
#define CP_COMMIT() asm volatile("cp.async.commit_group;")
#define CP_WAIT1()  asm volatile("cp.async.wait_group 1;")
#define CP_WAIT0()  asm volatile("cp.async.wait_group 0;")

#define LDSM4(r, addr) \
    asm volatile("ldmatrix.sync.aligned.m8n8.x4.shared.b16 {%0,%1,%2,%3}, [%4];" \
        : "=r"((r)[0]), "=r"((r)[1]), "=r"((r)[2]), "=r"((r)[3]) : "r"(addr))
#define LDSM4T(r, addr) \
    asm volatile("ldmatrix.sync.aligned.m8n8.x4.trans.shared.b16 {%0,%1,%2,%3}, [%4];" \
        : "=r"((r)[0]), "=r"((r)[1]), "=r"((r)[2]), "=r"((r)[3]) : "r"(addr))

__device__ __forceinline__ void mma_f16(float* c,
    uint32_t a0, uint32_t a1, uint32_t a2, uint32_t a3, uint32_t b0, uint32_t b1)
{
    asm volatile(
        "mma.sync.aligned.m16n8k16.row.col.f32.f16.f16.f32 "
        "{%0,%1,%2,%3}, {%4,%5,%6,%7}, {%8,%9}, {%0,%1,%2,%3};"
        : "+f"(c[0]), "+f"(c[1]), "+f"(c[2]), "+f"(c[3])
        : "r"(a0), "r"(a1), "r"(a2), "r"(a3), "r"(b0), "r"(b1));
}

// ---------------------------------------------------------------------------
// Weight transpose (fp32 [K][N] -> half [N][K])
// ---------------------------------------------------------------------------
__device__ __forceinline__ void transpose_body(const float* __restrict__ in,
                                               __half* __restrict__ out, int K, int N)
{
    __shared__ float tile[64][65];
    int tid = threadIdx.x;
    int tx = tid & 63;
    int tg = tid >> 6;
    int x  = blockIdx.x * 64 + tx;
    int y0 = blockIdx.y * 64;
    #pragma unroll
    for (int i = 0; i < 16; i++) {
        int r = tg * 16 + i;
        tile[r][tx] = in[(size_t)(y0 + r) * N + x];
    }
    __syncthreads();
    int xo  = blockIdx.y * 64 + tx;
    int yo0 = blockIdx.x * 64;
    #pragma unroll
    for (int i = 0; i < 16; i++) {
        int r = tg * 16 + i;
        out[(size_t)(yo0 + r) * K + xo] = __float2half(tile[tx][r]);
    }
}

__global__ void transpose4_kernel(const float* __restrict__ w0, const float* __restrict__ w1,
                                  const float* __restrict__ w2, const float* __restrict__ w3,
                                  __half* __restrict__ o0, __half* __restrict__ o1,
                                  __half* __restrict__ o2, __half* __restrict__ o3)
{
    int z = blockIdx.z;
    const float* in = (z == 0) ? w0 : (z == 1) ? w1 : (z == 2) ? w2 : w3;
    __half* out     = (z == 0) ? o0 : (z == 1) ? o1 : (z == 2) ? o2 : o3;
    transpose_body(in, out, D_MODEL, D_MODEL);
}

__global__ void transpose2_kernel(const float* __restrict__ w1, const float* __restrict__ w2,
                                  __half* __restrict__ o1, __half* __restrict__ o2)
{
    if (blockIdx.z == 0) {
        if (blockIdx.x >= D_FF / 64 || blockIdx.y >= D_MODEL / 64) return;
        transpose_body(w1, o1, D_MODEL, D_FF);
    } else {
        if (blockIdx.x >= D_MODEL / 64 || blockIdx.y >= D_FF / 64) return;
        transpose_body(w2, o2, D_FF, D_MODEL);
    }
}

// ---------------------------------------------------------------------------
// LayerNorm: warp-per-row, fp32 in, half out. Block 256 = 8 rows.
// ---------------------------------------------------------------------------
__global__ void ln_kernel(const float* __restrict__ x, const float* __restrict__ g,
                          const float* __restrict__ b, __half* __restrict__ out)
{
    int wid  = threadIdx.x >> 5, lane = threadIdx.x & 31;
    int row  = blockIdx.x * 8 + wid;
    const float4* xr = (const float4*)(x + (size_t)row * D_MODEL);

    float4 v[8];
    float s = 0.f, ss = 0.f;
    #pragma unroll
    for (int i = 0; i < 8; i++) {
        v[i] = xr[i * 32 + lane];
        s  += v[i].x + v[i].y + v[i].z + v[i].w;
        ss += v[i].x*v[i].x + v[i].y*v[i].y + v[i].z*v[i].z + v[i].w*v[i].w;
    }
    #pragma unroll
    for (int o = 16; o > 0; o >>= 1) {
        s  += __shfl_xor_sync(0xffffffffu, s,  o);
        ss += __shfl_xor_sync(0xffffffffu, ss, o);
    }
    float mu   = s  * (1.0f / D_MODEL);
    float var  = ss * (1.0f / D_MODEL) - mu * mu;
    float rstd = rsqrtf(var + LN_EPS);

    const float4* gp = (const float4*)g;
    const float4* bp = (const float4*)b;
    __half* orow = out + (size_t)row * D_MODEL;
    #pragma unroll
    for (int i = 0; i < 8; i++) {
        int idx = i * 32 + lane;
        float4 gv = gp[idx];
        float4 bv = bp[idx];
        uint2 o2;
        o2.x = pack_f2h2((v[i].x - mu) * rstd * gv.x + bv.x,
                         (v[i].y - mu) * rstd * gv.y + bv.y);
        o2.y = pack_f2h2((v[i].z - mu) * rstd * gv.z + bv.z,
                         (v[i].w - mu) * rstd * gv.w + bv.w);
        *(uint2*)(orow + idx * 4) = o2;
    }
}

// ---------------------------------------------------------------------------
// fp16 mma GEMM: BM=BN=128, BK=32, 8 warps 2x4, warp 64x32, m16n8k16.
// ldmatrix fragments, 3-stage cp.async, 2 CTAs/SM.
// ---------------------------------------------------------------------------
#define BM 128
#define BN 128
#define BKh 32
#define LDH 40
#define ASZH (BM * LDH)
#define ASZB (ASZH * 2)
#define STAGEB (2 * ASZB)             // 20480
#define NSTAGE 3
#define GEMM_SMEM (NSTAGE * STAGEB)   // 61440

struct Frag { float c[4][4][4]; };

__device__ __forceinline__ void mma_mainloop(const __half* __restrict__ A,
                                             const __half* __restrict__ WT,
                                             int K, int row0, int col0,
                                             __half* sm, Frag& F)
{
    int tid  = threadIdx.x;
    int lane = tid & 31, wid = tid >> 5;
    int wm = wid >> 2, wn = wid & 3;
    int rr = lane & 7, mat = lane >> 3;

    uint32_t sbase = smem_u32(sm);

    int r0 = tid >> 2;
    int c8 = tid & 3;
    const __half* gA = A  + (size_t)(row0 + r0) * K + c8 * 8;
    const __half* gB = WT + (size_t)(col0 + r0) * K + c8 * 8;
    uint32_t stA0 = (uint32_t)((r0)      * LDH + c8 * 8) * 2;
    uint32_t stA1 = (uint32_t)((r0 + 64) * LDH + c8 * 8) * 2;
    uint32_t stB0 = stA0 + ASZB;
    uint32_t stB1 = stA1 + ASZB;

    uint32_t offA[2][4], offB[2][2];
    #pragma unroll
    for (int ks = 0; ks < 2; ks++) {
        #pragma unroll
        for (int mf = 0; mf < 4; mf++) {
            int row = wm * 64 + mf * 16 + rr + ((mat & 1) ? 8 : 0);
            int col = ks * 16 + ((mat & 2) ? 8 : 0);
            offA[ks][mf] = (uint32_t)(row * LDH + col) * 2;
        }
        #pragma unroll
        for (int pr = 0; pr < 2; pr++) {
            int row = wn * 32 + pr * 16 + rr + ((mat & 2) ? 8 : 0);
            int col = ks * 16 + ((mat & 1) ? 8 : 0);
            offB[ks][pr] = (uint32_t)(row * LDH + col) * 2 + ASZB;
        }
    }

    #pragma unroll
    for (int mf = 0; mf < 4; mf++)
        #pragma unroll
        for (int nf = 0; nf < 4; nf++)
            #pragma unroll
            for (int r = 0; r < 4; r++) F.c[mf][nf][r] = 0.f;

    int nk = K / BKh;

    #pragma unroll
    for (int s = 0; s < 2; s++) {
        uint32_t sb = sbase + s * STAGEB;
        CP_ASYNC(sb + stA0, gA + (size_t)s * BKh);
        CP_ASYNC(sb + stA1, gA + (size_t)64 * K + (size_t)s * BKh);
        CP_ASYNC(sb + stB0, gB + (size_t)s * BKh);
        CP_ASYNC(sb + stB1, gB + (size_t)64 * K + (size_t)s * BKh);
        CP_COMMIT();
    }

    uint32_t rdoff = 0, wroff = 2 * STAGEB;
    for (int kt = 0; kt < nk; kt++) {
        if (kt == nk - 1) { CP_WAIT0(); } else { CP_WAIT1(); }
        __syncthreads();

        if (kt + 2 < nk) {
            uint32_t sb = sbase + wroff;
            const __half* a = gA + (size_t)(kt + 2) * BKh;
            const __half* b = gB + (size_t)(kt + 2) * BKh;
            CP_ASYNC(sb + stA0, a);
            CP_ASYNC(sb + stA1, a + (size_t)64 * K);
            CP_ASYNC(sb + stB0, b);
            CP_ASYNC(sb + stB1, b + (size_t)64 * K);
            CP_COMMIT();
            wroff += STAGEB; if (wroff == NSTAGE * STAGEB) wroff = 0;
        }

        uint32_t sb = sbase + rdoff;
        rdoff += STAGEB; if (rdoff == NSTAGE * STAGEB) rdoff = 0;
        #pragma unroll
        for (int ks = 0; ks < 2; ks++) {
            uint32_t bb0[4], bb1[4];
            LDSM4(bb0, sb + offB[ks][0]);
            LDSM4(bb1, sb + offB[ks][1]);
            #pragma unroll
            for (int mf = 0; mf < 4; mf++) {
                uint32_t aa[4];
                LDSM4(aa, sb + offA[ks][mf]);
                mma_f16(F.c[mf][0], aa[0], aa[1], aa[2], aa[3], bb0[0], bb0[1]);
                mma_f16(F.c[mf][1], aa[0], aa[1], aa[2], aa[3], bb0[2], bb0[3]);
                mma_f16(F.c[mf][2], aa[0], aa[1], aa[2], aa[3], bb1[0], bb1[1]);
                mma_f16(F.c[mf][3], aa[0], aa[1], aa[2], aa[3], bb1[2], bb1[3]);
            }
        }
    }
}

// QKV: gridDim.z selects weight; writes head-permuted half [B*H, L, 64]
__global__ __launch_bounds__(256, 2)
void tc_gemm_qkv(const __half* __restrict__ A,
                 const __half* __restrict__ Wqt, const __half* __restrict__ Wkt,
                 const __half* __restrict__ Wvt,
                 const float* __restrict__ bq, const float* __restrict__ bk,
                 const float* __restrict__ bv,
                 __half* __restrict__ Cq, __half* __restrict__ Ck, __half* __restrict__ Cv)
{
    extern __shared__ __half sm[];
    int z = blockIdx.z;
    const __half* WT  = (z == 0) ? Wqt : (z == 1) ? Wkt : Wvt;
    const float* bias = (z == 0) ? bq  : (z == 1) ? bk  : bv;
    __half* C         = (z == 0) ? Cq  : (z == 1) ? Ck  : Cv;

    int row0 = blockIdx.y * BM;
    int col0 = blockIdx.x * BN;
    Frag F;
    mma_mainloop(A, WT, D_MODEL, row0, col0, sm, F);

    int lane = threadIdx.x & 31, wid = threadIdx.x >> 5;
    int wm = wid >> 2, wn = wid & 3;
    int group = lane >> 2, tig = lane & 3;

    #pragma unroll
    for (int mf = 0; mf < 4; mf++) {
        #pragma unroll
        for (int nf = 0; nf < 4; nf++) {
            int row = row0 + wm * 64 + mf * 16 + group;
            int col = col0 + wn * 32 + nf * 8 + 2 * tig;
            float2 bv2 = *(const float2*)(bias + col);
            int h = col >> 6, d = col & 63;
            #pragma unroll
            for (int hi = 0; hi < 2; hi++) {
                int r = row + hi * 8;
                int b = r >> 11, l = r & (SEQ - 1);
                __half2 o = __floats2half2_rn(F.c[mf][nf][hi * 2 + 0] + bv2.x,
                                              F.c[mf][nf][hi * 2 + 1] + bv2.y);
                *(__half2*)(C + (((size_t)(b * NHEAD + h) * SEQ) + l) * HEAD_DIM + d) = o;
            }
        }
    }
}

// MODE 1: half out = gelu(acc+bias).  MODE 2: float out = res + acc + bias.
template<int MODE>
__global__ __launch_bounds__(256, 2)
void tc_gemm(const __half* __restrict__ A, const __half* __restrict__ WT,
             const float* __restrict__ bias, const float* __restrict__ res,
             void* __restrict__ Cv, int N, int K)
{
    extern __shared__ __half sm[];
    int row0 = blockIdx.y * BM;
    int col0 = blockIdx.x * BN;
    Frag F;
    mma_mainloop(A, WT, K, row0, col0, sm, F);

    int lane = threadIdx.x & 31, wid = threadIdx.x >> 5;
    int wm = wid >> 2, wn = wid & 3;
    int group = lane >> 2, tig = lane & 3;

    #pragma unroll
    for (int mf = 0; mf < 4; mf++) {
        #pragma unroll
        for (int nf = 0; nf < 4; nf++) {
            int row = row0 + wm * 64 + mf * 16 + group;
            int col = col0 + wn * 32 + nf * 8 + 2 * tig;
            float2 bv2 = *(const float2*)(bias + col);
            #pragma unroll
            for (int hi = 0; hi < 2; hi++) {
                int r = row + hi * 8;
                float ox = F.c[mf][nf][hi * 2 + 0] + bv2.x;
                float oy = F.c[mf][nf][hi * 2 + 1] + bv2.y;
                if (MODE == 1) {
                    __half2 o = __floats2half2_rn(gelu_exact(ox), gelu_exact(oy));
                    *(__half2*)((__half*)Cv + (size_t)r * N + col) = o;
                } else {
                    float2 r2 = *(const float2*)(res + (size_t)r * N + col);
                    float2 o; o.x = ox + r2.x; o.y = oy + r2.y;
                    *(float2*)((float*)Cv + (size_t)r * N + col) = o;
                }
            }
        }
    }
}

// ---------------------------------------------------------------------------
// fp16 mma flash attention (causal). 128 q rows/block, 8 warps, 64-key tiles.
// K/V double-buffered via cp.async; heavy q-tiles scheduled first.
// ---------------------------------------------------------------------------
__global__ __launch_bounds__(256)
void attn_kernel(const __half* __restrict__ Q, const __half* __restrict__ K,
                 const __half* __restrict__ V, __half* __restrict__ out)
{
    __shared__ __half Qs[128][72];
    __shared__ __half KV[2][2][64][72];   // [buf][k/v][row][col]

    int tid = threadIdx.x;
    int lane = tid & 31, wid = tid >> 5;
    int group = lane >> 2, tig = lane & 3;
    int rr = lane & 7, mat = lane >> 3;
    int qb = (gridDim.x - 1 - blockIdx.x) * 128;   // heavy tiles first
    int bh = blockIdx.y;
    int wb = wid * 16;

    const __half* Qb = Q + (size_t)bh * SEQ * HEAD_DIM;
    const __half* Kb = K + (size_t)bh * SEQ * HEAD_DIM;
    const __half* Vb = V + (size_t)bh * SEQ * HEAD_DIM;

    #pragma unroll
    for (int i = 0; i < 4; i++) {
        int e = tid + i * 256;
        int r = e >> 3, c = e & 7;
        *(uint4*)&Qs[r][c * 8] = *(const uint4*)(Qb + (size_t)(qb + r) * HEAD_DIM + c * 8);
    }

    int lr[2], lc[2];
    uint32_t dK[2][2], dV[2][2];
    #pragma unroll
    for (int i = 0; i < 2; i++) {
        int e = tid + i * 256;
        lr[i] = e >> 3; lc[i] = (e & 7) * 8;
        #pragma unroll
        for (int buf = 0; buf < 2; buf++) {
            dK[buf][i] = smem_u32(&KV[buf][0][lr[i]][lc[i]]);
            dV[buf][i] = smem_u32(&KV[buf][1][lr[i]][lc[i]]);
        }
    }

    int nkt = (qb >> 6) + 2;

    #pragma unroll
    for (int i = 0; i < 2; i++) {
        CP_ASYNC(dK[0][i], Kb + (size_t)lr[i] * HEAD_DIM + lc[i]);
        CP_ASYNC(dV[0][i], Vb + (size_t)lr[i] * HEAD_DIM + lc[i]);
    }
    CP_COMMIT();

    __syncthreads();   // Qs visible

    uint32_t qa[4][4];
    #pragma unroll
    for (int ks = 0; ks < 4; ks++) {
        int kb = ks * 16 + 2 * tig;
        qa[ks][0] = *(const uint32_t*)&Qs[wb + group][kb];
        qa[ks][1] = *(const uint32_t*)&Qs[wb + group + 8][kb];
        qa[ks][2] = *(const uint32_t*)&Qs[wb + group][kb + 8];
        qa[ks][3] = *(const uint32_t*)&Qs[wb + group + 8][kb + 8];
    }

    uint32_t offK[4], offV[4];
    #pragma unroll
    for (int p = 0; p < 4; p++) {
        offK[p] = smem_u32(&KV[0][0][p * 16 + rr + ((mat & 2) ? 8 : 0)][(mat & 1) ? 8 : 0]);
        offV[p] = smem_u32(&KV[0][1][rr + ((mat & 1) ? 8 : 0)][p * 16 + ((mat & 2) ? 8 : 0)]);
    }
    const uint32_t BUFB = (uint32_t)sizeof(KV[0]);   // 18432 bytes

    float o[8][4];
    #pragma unroll
    for (int i = 0; i < 8; i++)
        #pragma unroll
        for (int j = 0; j < 4; j++) o[i][j] = 0.f;
    float m2[2] = {-1e30f, -1e30f};
    float l2[2] = {0.f, 0.f};

    const float scale = 0.125f;
    int row_g0 = qb + wb + group;

    for (int kt = 0; kt < nkt; kt++) {
        __syncthreads();   // readers of the refill target buffer are done

        if (kt + 1 < nkt) {
            int nb = (kt + 1) & 1;
            const __half* kp = Kb + (size_t)(kt + 1) * 64 * HEAD_DIM;
            const __half* vp = Vb + (size_t)(kt + 1) * 64 * HEAD_DIM;
            #pragma unroll
            for (int i = 0; i < 2; i++) {
                CP_ASYNC(dK[nb][i], kp + (size_t)lr[i] * HEAD_DIM + lc[i]);
                CP_ASYNC(dV[nb][i], vp + (size_t)lr[i] * HEAD_DIM + lc[i]);
            }
            CP_COMMIT();
            CP_WAIT1();
        } else {
            CP_WAIT0();
        }
        __syncthreads();   // current buffer visible

        uint32_t bsel = (kt & 1) ? BUFB : 0;

        bool active = (kt * 64) <= (qb + wb + 15);
        if (active) {
            float s[8][4];
            #pragma unroll
            for (int nf = 0; nf < 8; nf++)
                #pragma unroll
                for (int c = 0; c < 4; c++) s[nf][c] = 0.f;
            #pragma unroll
            for (int ks = 0; ks < 4; ks++) {
                #pragma unroll
                for (int p = 0; p < 4; p++) {
                    uint32_t kb4[4];
                    LDSM4(kb4, offK[p] + bsel + ks * 32);
                    mma_f16(s[2*p],   qa[ks][0], qa[ks][1], qa[ks][2], qa[ks][3], kb4[0], kb4[1]);
                    mma_f16(s[2*p+1], qa[ks][0], qa[ks][1], qa[ks][2], qa[ks][3], kb4[2], kb4[3]);
                }
            }

            bool need_mask = (kt * 64 + 63) > (qb + wb);
            #pragma unroll
            for (int nf = 0; nf < 8; nf++) {
                #pragma unroll
                for (int c = 0; c < 4; c++) {
                    float v = s[nf][c] * scale;
                    if (need_mask) {
                        int key = kt * 64 + nf * 8 + 2 * tig + (c & 1);
                        int rg  = row_g0 + ((c >= 2) ? 8 : 0);
                        if (key > rg) v = -1e30f;
                    }
                    s[nf][c] = v;
                }
            }

            #pragma unroll
            for (int r = 0; r < 2; r++) {
                float mx = -1e30f;
                #pragma unroll
                for (int nf = 0; nf < 8; nf++)
                    mx = fmaxf(mx, fmaxf(s[nf][2 * r], s[nf][2 * r + 1]));
                mx = fmaxf(mx, __shfl_xor_sync(0xffffffffu, mx, 1));
                mx = fmaxf(mx, __shfl_xor_sync(0xffffffffu, mx, 2));
                float mnew = fmaxf(m2[r], mx);
                float corr = __expf(m2[r] - mnew);
                float rsum = 0.f;
                #pragma unroll
                for (int nf = 0; nf < 8; nf++) {
                    float p0 = __expf(s[nf][2 * r]     - mnew);
                    float p1 = __expf(s[nf][2 * r + 1] - mnew);
                    s[nf][2 * r] = p0; s[nf][2 * r + 1] = p1;
                    rsum += p0 + p1;
                }
                rsum += __shfl_xor_sync(0xffffffffu, rsum, 1);
                rsum += __shfl_xor_sync(0xffffffffu, rsum, 2);
                l2[r] = l2[r] * corr + rsum;
                m2[r] = mnew;
                #pragma unroll
                for (int nfd = 0; nfd < 8; nfd++) {
                    o[nfd][2 * r]     *= corr;
                    o[nfd][2 * r + 1] *= corr;
                }
            }

            #pragma unroll
            for (int ks = 0; ks < 4; ks++) {
                uint32_t pa0 = pack_f2h2(s[2*ks][0],   s[2*ks][1]);
                uint32_t pa1 = pack_f2h2(s[2*ks][2],   s[2*ks][3]);
                uint32_t pa2 = pack_f2h2(s[2*ks+1][0], s[2*ks+1][1]);
                uint32_t pa3 = pack_f2h2(s[2*ks+1][2], s[2*ks+1][3]);
                #pragma unroll
                for (int p = 0; p < 4; p++) {
                    uint32_t vb4[4];
                    LDSM4T(vb4, offV[p] + bsel + ks * (16 * 72 * 2));
                    mma_f16(o[2*p],   pa0, pa1, pa2, pa3, vb4[0], vb4[1]);
                    mma_f16(o[2*p+1], pa0, pa1, pa2, pa3, vb4[2], vb4[3]);
                }
            }
        }
    }

    int b = bh >> 4, h = bh & 15;
    float inv0 = 1.0f / l2[0];
    float inv1 = 1.0f / l2[1];
    #pragma unroll
    for (int r = 0; r < 2; r++) {
        int rg = row_g0 + r * 8;
        int l = rg & (SEQ - 1);
        float inv = r ? inv1 : inv0;
        #pragma unroll
        for (int nfd = 0; nfd < 8; nfd++) {
            int d = nfd * 8 + 2 * tig;
            __half2 ov = __floats2half2_rn(o[nfd][2 * r] * inv, o[nfd][2 * r + 1] * inv);
            *(__half2*)(out + ((size_t)(b * SEQ + l)) * D_MODEL + h * HEAD_DIM + d) = ov;
        }
    }
}

// ---------------------------------------------------------------------------
// Launch: ALL weight transposes on side stream; LN1 overlaps transpose4.
// ---------------------------------------------------------------------------
extern "C" void kernel_launch(void* const* d_in, const int* in_sizes, int n_in,
                              void* d_out, int out_size)
{
    const float* x   = (const float*)d_in[0];
    const float* Wq  = (const float*)d_in[2];
    const float* bq  = (const float*)d_in[3];
    const float* Wk  = (const float*)d_in[4];
    const float* bk  = (const float*)d_in[5];
    const float* Wv  = (const float*)d_in[6];
    const float* bv  = (const float*)d_in[7];
    const float* Wo  = (const float*)d_in[8];
    const float* bo  = (const float*)d_in[9];
    const float* g1  = (const float*)d_in[10];
    const float* b1  = (const float*)d_in[11];
    const float* g2  = (const float*)d_in[12];
    const float* b2  = (const float*)d_in[13];
    const float* W1  = (const float*)d_in[14];
    const float* bf1 = (const float*)d_in[15];
    const float* W2  = (const float*)d_in[16];
    const float* bf2 = (const float*)d_in[17];
    float* out = (float*)d_out;

    __half *p_nx, *p_q, *p_k, *p_v, *p_attn, *p_nx2, *p_ffh;
    __half *p_wqt, *p_wkt, *p_wvt, *p_wot, *p_w1t, *p_w2t;
    float *p_x1;
    cudaGetSymbolAddress((void**)&p_nx,   g_nx);
    cudaGetSymbolAddress((void**)&p_q,    g_q);
    cudaGetSymbolAddress((void**)&p_k,    g_k);
    cudaGetSymbolAddress((void**)&p_v,    g_v);
    cudaGetSymbolAddress((void**)&p_attn, g_attn);
    cudaGetSymbolAddress((void**)&p_x1,   g_x1);
    cudaGetSymbolAddress((void**)&p_nx2,  g_nx2);
    cudaGetSymbolAddress((void**)&p_ffh,  g_ffh);
    cudaGetSymbolAddress((void**)&p_wqt,  g_wqt);
    cudaGetSymbolAddress((void**)&p_wkt,  g_wkt);
    cudaGetSymbolAddress((void**)&p_wvt,  g_wvt);
    cudaGetSymbolAddress((void**)&p_wot,  g_wot);
    cudaGetSymbolAddress((void**)&p_w1t,  g_w1t);
    cudaGetSymbolAddress((void**)&p_w2t,  g_w2t);

    cudaFuncSetAttribute(tc_gemm_qkv, cudaFuncAttributeMaxDynamicSharedMemorySize, GEMM_SMEM);
    cudaFuncSetAttribute(tc_gemm<1>,  cudaFuncAttributeMaxDynamicSharedMemorySize, GEMM_SMEM);
    cudaFuncSetAttribute(tc_gemm<2>,  cudaFuncAttributeMaxDynamicSharedMemorySize, GEMM_SMEM);

    static cudaStream_t s2 = nullptr;
    static cudaEvent_t evFork = nullptr, evT4 = nullptr, evJoin = nullptr;
    if (!s2) {
        cudaStreamCreateWithFlags(&s2, cudaStreamNonBlocking);
        cudaEventCreateWithFlags(&evFork, cudaEventDisableTiming);
        cudaEventCreateWithFlags(&evT4,   cudaEventDisableTiming);
        cudaEventCreateWithFlags(&evJoin, cudaEventDisableTiming);
    }

    dim3 t256(256);

    // fork: ALL weight transposes on side stream
    cudaEventRecord(evFork, 0);
    cudaStreamWaitEvent(s2, evFork, 0);
    transpose4_kernel<<<dim3(D_MODEL/64, D_MODEL/64, 4), t256, 0, s2>>>(
        Wq, Wk, Wv, Wo, p_wqt, p_wkt, p_wvt, p_wot);
    cudaEventRecord(evT4, s2);
    transpose2_kernel<<<dim3(D_FF/64, D_FF/64, 2), t256, 0, s2>>>(W1, W2, p_w1t, p_w2t);
    cudaEventRecord(evJoin, s2);

    // 1. nx = LN1(x)  (no dependency on transposes; overlaps transpose4)
    ln_kernel<<<MROWS / 8, t256>>>(x, g1, b1, p_nx);

    // join: QKV/O transposes ready
    cudaStreamWaitEvent(0, evT4, 0);

    // 2. Q/K/V
    dim3 gQKV(D_MODEL / BN, MROWS / BM, 3);
    tc_gemm_qkv<<<gQKV, t256, GEMM_SMEM>>>(p_nx, p_wqt, p_wkt, p_wvt,
                                           bq, bk, bv, p_q, p_k, p_v);

    // 3. causal flash attention (K/V double-buffered)
    dim3 gAttn(SEQ / 128, BATCH * NHEAD);
    attn_kernel<<<gAttn, t256>>>(p_q, p_k, p_v, p_attn);

    // 4. x1 = x + attn @ Wo + bo
    dim3 gD(D_MODEL / BN, MROWS / BM);
    tc_gemm<2><<<gD, t256, GEMM_SMEM>>>(p_attn, p_wot, bo, x, p_x1, D_MODEL, D_MODEL);

    // 5. nx2 = LN2(x1)
    ln_kernel<<<MROWS / 8, t256>>>(p_x1, g2, b2, p_nx2);

    // join: W1/W2 transposes must be done before FFN1
    cudaStreamWaitEvent(0, evJoin, 0);

    // 6. h = gelu(nx2 @ W1 + bf1)
    dim3 gF1(D_FF / BN, MROWS / BM);
    tc_gemm<1><<<gF1, t256, GEMM_SMEM>>>(p_nx2, p_w1t, bf1, nullptr, p_ffh, D_FF, D_MODEL);

    // 7. out = x1 + h @ W2 + bf2
    tc_gemm<2><<<gD, t256, GEMM_SMEM>>>(p_ffh, p_w2t, bf2, p_x1, out, D_MODEL, D_FF);
}